// round 14
// baseline (speedup 1.0000x reference)
#include <cuda_runtime.h>
#include <cuda_fp16.h>
#include <cstdint>
#include <math.h>

#define BB   2
#define TT   2048
#define DM   1024
#define NH   16
#define DKH  64
#define MTOK (BB*TT)     // 4096

// Scratch (allocation-free), all fp16 operands
__device__ __half g_QI[MTOK*DM];
__device__ __half g_KI[MTOK*DM];
__device__ __half g_VI[MTOK*DM];
__device__ __half g_Q[MTOK*DM];     // Q proj, prescaled 0.125*log2e
__device__ __half g_K[MTOK*DM];
__device__ __half g_VT[DM*MTOK];    // V proj transposed [channel][token]
__device__ __half g_C[MTOK*DM];
__device__ __half g_WT[4][DM*DM];   // weights transposed [n][k]

#define LOG2E 1.4426950408889634f

__device__ __forceinline__ uint32_t smem_u32(const void* p) {
    uint32_t a;
    asm("{ .reg .u64 t; cvta.to.shared.u64 t, %1; cvt.u32.u64 %0, t; }" : "=r"(a) : "l"(p));
    return a;
}
__device__ __forceinline__ float fexp2(float x) {
    float y; asm("ex2.approx.f32 %0, %1;" : "=f"(y) : "f"(x)); return y;
}
__device__ __forceinline__ uint32_t pack_h2(float lo, float hi) {
    uint32_t r;
    asm("cvt.rn.f16x2.f32 %0, %1, %2;" : "=r"(r) : "f"(hi), "f"(lo));
    return r;
}
__device__ __forceinline__ void mma_f16(float* c, const uint32_t* a, const uint32_t* b) {
    asm volatile(
        "mma.sync.aligned.m16n8k16.row.col.f32.f16.f16.f32 "
        "{%0,%1,%2,%3}, {%4,%5,%6,%7}, {%8,%9}, {%0,%1,%2,%3};"
        : "+f"(c[0]), "+f"(c[1]), "+f"(c[2]), "+f"(c[3])
        : "r"(a[0]), "r"(a[1]), "r"(a[2]), "r"(a[3]), "r"(b[0]), "r"(b[1]));
}
#define LDSM_X4(r0,r1,r2,r3,addr) \
    asm volatile("ldmatrix.sync.aligned.m8n8.x4.shared.b16 {%0,%1,%2,%3}, [%4];" \
        : "=r"(r0), "=r"(r1), "=r"(r2), "=r"(r3) : "r"(addr))
#define CP_ASYNC16(dst, src) \
    asm volatile("cp.async.cg.shared.global [%0], [%1], 16;" :: "r"(dst), "l"(src))
#define CP_COMMIT()  asm volatile("cp.async.commit_group;" ::: "memory")
#define CP_WAIT2()   asm volatile("cp.async.wait_group 2;" ::: "memory")
#define CP_WAIT1()   asm volatile("cp.async.wait_group 1;" ::: "memory")

// ===========================================================================
// Weight transpose + fp16 convert: out[n*K+k] = half(in[k*N+n])
// ===========================================================================
__global__ __launch_bounds__(256) void transpose_h_x4(
    const float* __restrict__ w0, const float* __restrict__ w1,
    const float* __restrict__ w2, const float* __restrict__ w3,
    __half* __restrict__ o0, __half* __restrict__ o1,
    __half* __restrict__ o2, __half* __restrict__ o3)
{
    const float* in  = (blockIdx.z == 0) ? w0 : (blockIdx.z == 1) ? w1 :
                       (blockIdx.z == 2) ? w2 : w3;
    __half*      out = (blockIdx.z == 0) ? o0 : (blockIdx.z == 1) ? o1 :
                       (blockIdx.z == 2) ? o2 : o3;
    __shared__ float t[32][33];
    int tx = threadIdx.x & 31;
    int ty = threadIdx.x >> 5;
    int x  = blockIdx.x*32 + tx;
    int y0 = blockIdx.y*32;
    #pragma unroll
    for (int j = ty; j < 32; j += 8) t[j][tx] = in[(size_t)(y0+j)*DM + x];
    __syncthreads();
    int xo  = y0 + tx;
    int yo0 = blockIdx.x*32;
    #pragma unroll
    for (int j = ty; j < 32; j += 8)
        out[(size_t)(yo0+j)*DM + xo] = __float2half_rn(t[tx][j]);
}

// ===========================================================================
// Elementwise fp32 -> fp16 preround for q,k,v inputs
// ===========================================================================
__global__ __launch_bounds__(256) void preround_h(
    const float* __restrict__ q, const float* __restrict__ k,
    const float* __restrict__ v,
    __half* __restrict__ oq, __half* __restrict__ ok, __half* __restrict__ ov)
{
    const float* in = (blockIdx.z == 0) ? q : (blockIdx.z == 1) ? k : v;
    __half*     out = (blockIdx.z == 0) ? oq : (blockIdx.z == 1) ? ok : ov;
    int idx = blockIdx.x*256 + threadIdx.x;
    float4 f = ((const float4*)in)[idx];
    uint2 u;
    u.x = pack_h2(f.x, f.y);
    u.y = pack_h2(f.z, f.w);
    ((uint2*)out)[idx] = u;
}

// ===========================================================================
// fp16 GEMM core: 128(M) x 128(N) CTA tile, 256 threads (8 warps, 4m x 2n),
// K-chunk 64 halves (128B rows), 3-stage cp.async, 2 CTAs/SM.
// Loop order: compute(c) -> barrier -> copy(c+3) into freed stage.
// mode 0: fp32 out; mode 1: half(x*scl); mode 2: transposed half out
// ===========================================================================
#define NCH      16
#define STG_B    32768                // A 16KB + B 16KB
#define GM_SMEM  (3*STG_B)            // 96 KB -> 2 CTAs/SM

__device__ __forceinline__ void gemm_core(
    const __half* __restrict__ A, const __half* __restrict__ WT,
    const float* __restrict__ bias, void* __restrict__ Cv,
    float scl, int mode, char* dsm)
{
    const uint32_t smb = smem_u32(dsm);

    const int tid  = threadIdx.x;
    const int wid  = tid >> 5;
    const int lane = tid & 31;
    const int wm   = wid >> 1;
    const int wn   = wid & 1;
    const int g    = lane >> 2;
    const int t    = lane & 3;
    const int rowBase = blockIdx.y * 128;
    const int colBase = blockIdx.x * 128;

    const int lr = lane & 7;
    const int lh = (lane >> 3) & 1;
    const int lg = lane >> 4;
    const int rowA0 = wm*32 + lr + 8*lh;
    const int rowB0 = wn*64 + lr + 8*lh;

    float acc[2][8][4];
    #pragma unroll
    for (int i = 0; i < 2; ++i)
        #pragma unroll
        for (int j = 0; j < 8; ++j)
            #pragma unroll
            for (int e = 0; e < 4; ++e) acc[i][j][e] = 0.f;

    auto copy_chunk = [&](int c, int stage) {
        const int k0 = c * 64;
        const uint32_t sb = smb + stage*STG_B;
        #pragma unroll
        for (int i = 0; i < 4; ++i) {
            int idx = tid + i*256;
            int row = idx >> 3;
            int gg  = idx & 7;
            uint32_t dst = sb + row*128 + 16*(gg ^ (row & 7));
            CP_ASYNC16(dst, A + (size_t)(rowBase+row)*DM + k0 + gg*8);
        }
        #pragma unroll
        for (int i = 0; i < 4; ++i) {
            int idx = tid + i*256;
            int row = idx >> 3;
            int gg  = idx & 7;
            uint32_t dst = sb + 16384 + row*128 + 16*(gg ^ (row & 7));
            CP_ASYNC16(dst, WT + (size_t)(colBase+row)*DM + k0 + gg*8);
        }
    };

    auto compute = [&](int stage) {
        const uint32_t sa  = smb + stage*STG_B;
        const uint32_t sbB = sa + 16384;
        #pragma unroll
        for (int ks = 0; ks < 4; ++ks) {
            const uint32_t swg = 16u * ((2*ks + lg) ^ lr);
            uint32_t a0[4], a1[4];
            LDSM_X4(a0[0],a0[1],a0[2],a0[3], sa + (rowA0     )*128 + swg);
            LDSM_X4(a1[0],a1[1],a1[2],a1[3], sa + (rowA0 + 16)*128 + swg);
            #pragma unroll
            for (int p = 0; p < 4; ++p) {
                uint32_t bq[4];
                LDSM_X4(bq[0],bq[1],bq[2],bq[3], sbB + (rowB0 + p*16)*128 + swg);
                uint32_t be[2] = {bq[0], bq[2]};
                uint32_t bo[2] = {bq[1], bq[3]};
                mma_f16(acc[0][2*p],   a0, be);
                mma_f16(acc[1][2*p],   a1, be);
                mma_f16(acc[0][2*p+1], a0, bo);
                mma_f16(acc[1][2*p+1], a1, bo);
            }
        }
    };

    copy_chunk(0, 0); CP_COMMIT();
    copy_chunk(1, 1); CP_COMMIT();
    copy_chunk(2, 2); CP_COMMIT();

    for (int c = 0; c < NCH; ++c) {
        CP_WAIT2();
        __syncthreads();                 // chunk c resident in stage c%3
        compute(c % 3);
        __syncthreads();                 // stage c%3 fully consumed
        if (c + 3 < NCH) copy_chunk(c + 3, c % 3);
        CP_COMMIT();
    }

    #pragma unroll
    for (int mt = 0; mt < 2; ++mt) {
        int r0 = rowBase + wm*32 + mt*16 + g;
        #pragma unroll
        for (int nt = 0; nt < 8; ++nt) {
            int col = colBase + wn*64 + nt*8 + 2*t;
            float b0 = bias[col], b1 = bias[col+1];
            float v00 = acc[mt][nt][0] + b0, v01 = acc[mt][nt][1] + b1;
            float v10 = acc[mt][nt][2] + b0, v11 = acc[mt][nt][3] + b1;
            if (mode == 0) {
                float* C = (float*)Cv;
                *(float2*)(C + (size_t)r0*DM + col)     = make_float2(v00, v01);
                *(float2*)(C + (size_t)(r0+8)*DM + col) = make_float2(v10, v11);
            } else if (mode == 1) {
                __half* C = (__half*)Cv;
                *(uint32_t*)(C + (size_t)r0*DM + col)     = pack_h2(v00*scl, v01*scl);
                *(uint32_t*)(C + (size_t)(r0+8)*DM + col) = pack_h2(v10*scl, v11*scl);
            } else {
                __half* C = (__half*)Cv;
                C[(size_t)col*MTOK + r0]         = __float2half_rn(v00);
                C[(size_t)(col+1)*MTOK + r0]     = __float2half_rn(v01);
                C[(size_t)col*MTOK + r0 + 8]     = __float2half_rn(v10);
                C[(size_t)(col+1)*MTOK + r0 + 8] = __float2half_rn(v11);
            }
        }
    }
}

__global__ __launch_bounds__(256, 2) void gemm_qkv(
    const __half* __restrict__ qi, const __half* __restrict__ ki, const __half* __restrict__ vi,
    const __half* __restrict__ wtq, const __half* __restrict__ wtk, const __half* __restrict__ wtv,
    const float* __restrict__ bq, const float* __restrict__ bk, const float* __restrict__ bv,
    __half* __restrict__ oq, __half* __restrict__ ok, __half* __restrict__ ovt)
{
    extern __shared__ char dsm[];
    const int z = blockIdx.z;
    const __half* A  = (z == 0) ? qi  : (z == 1) ? ki  : vi;
    const __half* WT = (z == 0) ? wtq : (z == 1) ? wtk : wtv;
    const float*  bb = (z == 0) ? bq  : (z == 1) ? bk  : bv;
    __half*       C  = (z == 0) ? oq  : (z == 1) ? ok  : ovt;
    float scl = (z == 0) ? 0.125f * LOG2E : 1.0f;
    int mode  = (z == 2) ? 2 : 1;
    gemm_core(A, WT, bb, C, scl, mode, dsm);
}

__global__ __launch_bounds__(256, 2) void gemm_out(
    const __half* __restrict__ A, const __half* __restrict__ WT,
    const float* __restrict__ bias, float* __restrict__ C)
{
    extern __shared__ char dsm[];
    gemm_core(A, WT, bias, C, 1.0f, 0, dsm);
}

// ===========================================================================
// fp16 tensor-core causal flash attention: 64 q-rows per CTA, 4 warps,
// 4 CTAs/SM. P in registers; Q fragments PERSISTENT in registers (loaded
// once); rescale skipped when running max unchanged (bit-identical).
// smem (40KB): [0,8K) Q; [8K + st*16K) st=0,1: K 8KB + VT 8KB
// ===========================================================================
#define AQ_ROWS 64
#define AKV     64
#define AOFF_KV 8192
#define ATTN_SMEM_TC (AOFF_KV + 2*16384)   // 40 KB

__global__ __launch_bounds__(128, 4) void attn_tc(
    const __half* __restrict__ Q, const __half* __restrict__ K,
    const __half* __restrict__ VT, __half* __restrict__ O)
{
    extern __shared__ char smraw[];
    const uint32_t smb = smem_u32(smraw);

    const int tid  = threadIdx.x;
    const int wid  = tid >> 5;            // 0..3
    const int lane = tid & 31;
    const int g    = lane >> 2;
    const int t4   = lane & 3;
    const int lr   = lane & 7;
    const int lh   = (lane >> 3) & 1;
    const int lg   = lane >> 4;
    const int h    = blockIdx.y;
    const int b    = blockIdx.z;
    const int q0   = (gridDim.x - 1 - blockIdx.x) * AQ_ROWS;  // longest first

    const int qi0 = q0 + wid*16 + g;
    const int qi1 = qi0 + 8;

    const __half* Qb  = Q + ((size_t)(b*TT))*DM + h*DKH;
    const __half* Kb  = K + ((size_t)(b*TT))*DM + h*DKH;
    const __half* VTb = VT + (size_t)(h*DKH)*MTOK + b*TT;

    const int ntiles = q0/AKV + 1;

    auto copy_kv = [&](int tile, int st) {
        const int k0 = tile * AKV;
        const uint32_t base = smb + AOFF_KV + st*16384;
        #pragma unroll
        for (int i = 0; i < 4; ++i) {           // K: 64 rows x 8 granules
            int idx = tid + i*128;
            int row = idx >> 3;
            int gg  = idx & 7;
            uint32_t dst = base + row*128 + 16*(gg ^ (row & 7));
            CP_ASYNC16(dst, Kb + (size_t)(k0+row)*DM + gg*8);
        }
        #pragma unroll
        for (int i = 0; i < 4; ++i) {           // VT: 64 d-rows x 8 granules
            int idx = tid + i*128;
            int row = idx >> 3;
            int gg  = idx & 7;
            uint32_t dst = base + 8192 + row*128 + 16*(gg ^ (row & 7));
            CP_ASYNC16(dst, VTb + (size_t)row*MTOK + k0 + gg*8);
        }
    };

    // ---- prologue: Q staging + first (up to) 2 KV tiles ----
    #pragma unroll
    for (int i = 0; i < 4; ++i) {               // Q: 64 rows x 8 granules
        int idx = tid + i*128;
        int row = idx >> 3;
        int gg  = idx & 7;
        uint32_t dst = smb + row*128 + 16*(gg ^ (row & 7));
        CP_ASYNC16(dst, Qb + (size_t)(q0+row)*DM + gg*8);
    }
    copy_kv(0, 0); CP_COMMIT();
    if (1 < ntiles) copy_kv(1, 1);
    CP_COMMIT();

    float oacc[8][4];
    #pragma unroll
    for (int nt = 0; nt < 8; ++nt)
        #pragma unroll
        for (int e = 0; e < 4; ++e) oacc[nt][e] = 0.f;
    float m0 = -1e30f, m1 = -1e30f, l0 = 0.f, l1 = 0.f;

    const int frow = lr + 8*lh;
    const int qrow = wid*16 + frow;

    // ---- load Q fragments ONCE into persistent registers ----
    CP_WAIT1();
    __syncthreads();
    uint32_t qa[4][4];
    #pragma unroll
    for (int ks = 0; ks < 4; ++ks)
        LDSM_X4(qa[ks][0], qa[ks][1], qa[ks][2], qa[ks][3],
                smb + qrow*128 + 16u*((2*ks + lg) ^ lr));

    for (int tk = 0; tk < ntiles; ++tk) {
        CP_WAIT1();
        __syncthreads();
        const uint32_t sK = smb + AOFF_KV + (tk & 1)*16384;
        const uint32_t sV = sK + 8192;

        // ---- S = Q @ K^T ----
        float sf[8][4];
        #pragma unroll
        for (int nt = 0; nt < 8; ++nt)
            #pragma unroll
            for (int e = 0; e < 4; ++e) sf[nt][e] = 0.f;
        #pragma unroll
        for (int ks = 0; ks < 4; ++ks) {
            const uint32_t swg = 16u * ((2*ks + lg) ^ lr);
            #pragma unroll
            for (int p = 0; p < 4; ++p) {
                uint32_t bq[4];
                LDSM_X4(bq[0],bq[1],bq[2],bq[3], sK + (p*16 + frow)*128 + swg);
                uint32_t be[2] = {bq[0], bq[2]};
                uint32_t bo[2] = {bq[1], bq[3]};
                mma_f16(sf[2*p],   qa[ks], be);
                mma_f16(sf[2*p+1], qa[ks], bo);
            }
        }

        // ---- causal mask (last tile only) + row max ----
        float rmax0 = -1e30f, rmax1 = -1e30f;
        if (tk == ntiles - 1) {
            const int k0 = tk * AKV;
            #pragma unroll
            for (int nt = 0; nt < 8; ++nt) {
                int jb = k0 + nt*8 + 2*t4;
                #pragma unroll
                for (int e = 0; e < 4; ++e) {
                    int j = jb + (e & 1);
                    float v = sf[nt][e];
                    int qr = (e < 2) ? qi0 : qi1;
                    v = (j > qr) ? -1e30f : v;
                    sf[nt][e] = v;
                    if (e < 2) rmax0 = fmaxf(rmax0, v);
                    else       rmax1 = fmaxf(rmax1, v);
                }
            }
        } else {
            #pragma unroll
            for (int nt = 0; nt < 8; ++nt) {
                rmax0 = fmaxf(rmax0, fmaxf(sf[nt][0], sf[nt][1]));
                rmax1 = fmaxf(rmax1, fmaxf(sf[nt][2], sf[nt][3]));
            }
        }
        rmax0 = fmaxf(rmax0, __shfl_xor_sync(0xffffffff, rmax0, 1));
        rmax0 = fmaxf(rmax0, __shfl_xor_sync(0xffffffff, rmax0, 2));
        rmax1 = fmaxf(rmax1, __shfl_xor_sync(0xffffffff, rmax1, 1));
        rmax1 = fmaxf(rmax1, __shfl_xor_sync(0xffffffff, rmax1, 2));

        // ---- rescale only when running max actually changes (exact skip) ----
        if (!__all_sync(0xffffffff, (rmax0 <= m0) & (rmax1 <= m1))) {
            float mn0 = fmaxf(m0, rmax0);
            float mn1 = fmaxf(m1, rmax1);
            float c0 = fexp2(m0 - mn0);
            float c1 = fexp2(m1 - mn1);
            m0 = mn0; m1 = mn1;
            l0 *= c0; l1 *= c1;
            #pragma unroll
            for (int nt = 0; nt < 8; ++nt) {
                oacc[nt][0] *= c0; oacc[nt][1] *= c0;
                oacc[nt][2] *= c1; oacc[nt][3] *= c1;
            }
        }

        // ---- exp -> P directly as PV A-fragments ----
        float s0 = 0.f, s1 = 0.f;
        uint32_t pa[4][4];
        #pragma unroll
        for (int s = 0; s < 4; ++s) {
            float e00 = fexp2(sf[2*s  ][0] - m0), e01 = fexp2(sf[2*s  ][1] - m0);
            float e02 = fexp2(sf[2*s  ][2] - m1), e03 = fexp2(sf[2*s  ][3] - m1);
            float e10 = fexp2(sf[2*s+1][0] - m0), e11 = fexp2(sf[2*s+1][1] - m0);
            float e12 = fexp2(sf[2*s+1][2] - m1), e13 = fexp2(sf[2*s+1][3] - m1);
            s0 += (e00 + e01) + (e10 + e11);
            s1 += (e02 + e03) + (e12 + e13);
            pa[s][0] = pack_h2(e00, e01);
            pa[s][1] = pack_h2(e02, e03);
            pa[s][2] = pack_h2(e10, e11);
            pa[s][3] = pack_h2(e12, e13);
        }
        s0 += __shfl_xor_sync(0xffffffff, s0, 1);
        s0 += __shfl_xor_sync(0xffffffff, s0, 2);
        s1 += __shfl_xor_sync(0xffffffff, s1, 1);
        s1 += __shfl_xor_sync(0xffffffff, s1, 2);
        l0 += s0;
        l1 += s1;

        // ---- O += P @ V ----
        #pragma unroll
        for (int s = 0; s < 4; ++s) {
            const uint32_t swg = 16u * ((2*s + lg) ^ lr);
            #pragma unroll
            for (int p = 0; p < 4; ++p) {
                uint32_t bq[4];
                LDSM_X4(bq[0],bq[1],bq[2],bq[3], sV + (p*16 + frow)*128 + swg);
                uint32_t be[2] = {bq[0], bq[2]};
                uint32_t bo[2] = {bq[1], bq[3]};
                mma_f16(oacc[2*p],   pa[s], be);
                mma_f16(oacc[2*p+1], pa[s], bo);
            }
        }

        __syncthreads();
        if (tk + 2 < ntiles) copy_kv(tk + 2, tk & 1);
        CP_COMMIT();
    }

    // ---- epilogue ----
    const float i0 = 1.f / l0;
    const float i1 = 1.f / l1;
    __half* Ob = O + ((size_t)(b*TT))*DM + h*DKH;
    #pragma unroll
    for (int nt = 0; nt < 8; ++nt) {
        int d = nt*8 + 2*t4;
        *(uint32_t*)(Ob + (size_t)qi0*DM + d) = pack_h2(oacc[nt][0]*i0, oacc[nt][1]*i0);
        *(uint32_t*)(Ob + (size_t)qi1*DM + d) = pack_h2(oacc[nt][2]*i1, oacc[nt][3]*i1);
    }
}

// ===========================================================================
extern "C" void kernel_launch(void* const* d_in, const int* in_sizes, int n_in,
                              void* d_out, int out_size)
{
    const float* q  = (const float*)d_in[0];
    const float* k  = (const float*)d_in[1];
    const float* v  = (const float*)d_in[2];
    const float* wq = (const float*)d_in[4];
    const float* bq = (const float*)d_in[5];
    const float* wk = (const float*)d_in[6];
    const float* bk = (const float*)d_in[7];
    const float* wv = (const float*)d_in[8];
    const float* bv = (const float*)d_in[9];
    const float* wo = (const float*)d_in[10];
    const float* bo = (const float*)d_in[11];
    float* out = (float*)d_out;

    __half *gqi, *gki, *gvi, *gq, *gk, *gvt, *gc, *gwt;
    cudaGetSymbolAddress((void**)&gqi, g_QI);
    cudaGetSymbolAddress((void**)&gki, g_KI);
    cudaGetSymbolAddress((void**)&gvi, g_VI);
    cudaGetSymbolAddress((void**)&gq,  g_Q);
    cudaGetSymbolAddress((void**)&gk,  g_K);
    cudaGetSymbolAddress((void**)&gvt, g_VT);
    cudaGetSymbolAddress((void**)&gc,  g_C);
    cudaGetSymbolAddress((void**)&gwt, g_WT);
    __half* wtq = gwt;
    __half* wtk = gwt + (size_t)DM*DM;
    __half* wtv = gwt + (size_t)2*DM*DM;
    __half* wto = gwt + (size_t)3*DM*DM;

    cudaFuncSetAttribute(attn_tc, cudaFuncAttributeMaxDynamicSharedMemorySize, ATTN_SMEM_TC);
    cudaFuncSetAttribute(gemm_qkv, cudaFuncAttributeMaxDynamicSharedMemorySize, GM_SMEM);
    cudaFuncSetAttribute(gemm_out, cudaFuncAttributeMaxDynamicSharedMemorySize, GM_SMEM);

    dim3 tgrid(DM/32, DM/32, 4);
    transpose_h_x4<<<tgrid, 256>>>(wq, wk, wv, wo, wtq, wtk, wtv, wto);

    dim3 pgrid(MTOK*DM/4/256, 1, 3);
    preround_h<<<pgrid, 256>>>(q, k, v, gqi, gki, gvi);

    dim3 qkvgrid(DM/128, MTOK/128, 3);   // (8, 32, 3) = 768 CTAs, 2/SM
    gemm_qkv<<<qkvgrid, 256, GM_SMEM>>>(gqi, gki, gvi, wtq, wtk, wtv,
                                        bq, bk, bv, gq, gk, gvt);

    dim3 agrid(TT/AQ_ROWS, NH, BB);      // (32, 16, 2) = 1024 CTAs, 4/SM
    attn_tc<<<agrid, 128, ATTN_SMEM_TC>>>(gq, gk, gvt, gc);

    dim3 ogrid(DM/128, MTOK/128);        // (8, 32) = 256 CTAs = 1 full wave
    gemm_out<<<ogrid, 256, GM_SMEM>>>(gc, wto, bo, out);
}

// round 15
// speedup vs baseline: 1.0274x; 1.0274x over previous
#include <cuda_runtime.h>
#include <cuda_fp16.h>
#include <cstdint>
#include <math.h>

#define BB   2
#define TT   2048
#define DM   1024
#define NH   16
#define DKH  64
#define MTOK (BB*TT)     // 4096

// Scratch (allocation-free), all fp16 operands
__device__ __half g_QI[MTOK*DM];
__device__ __half g_KI[MTOK*DM];
__device__ __half g_VI[MTOK*DM];
__device__ __half g_Q[MTOK*DM];     // Q proj, prescaled 0.125*log2e
__device__ __half g_K[MTOK*DM];
__device__ __half g_VT[DM*MTOK];    // V proj transposed [channel][token]
__device__ __half g_C[MTOK*DM];
__device__ __half g_WT[4][DM*DM];   // weights transposed [n][k]

#define LOG2E 1.4426950408889634f

__device__ __forceinline__ uint32_t smem_u32(const void* p) {
    uint32_t a;
    asm("{ .reg .u64 t; cvta.to.shared.u64 t, %1; cvt.u32.u64 %0, t; }" : "=r"(a) : "l"(p));
    return a;
}
__device__ __forceinline__ float fexp2(float x) {
    float y; asm("ex2.approx.f32 %0, %1;" : "=f"(y) : "f"(x)); return y;
}
__device__ __forceinline__ uint32_t pack_h2(float lo, float hi) {
    uint32_t r;
    asm("cvt.rn.f16x2.f32 %0, %1, %2;" : "=r"(r) : "f"(hi), "f"(lo));
    return r;
}
__device__ __forceinline__ void mma_f16(float* c, const uint32_t* a, const uint32_t* b) {
    asm volatile(
        "mma.sync.aligned.m16n8k16.row.col.f32.f16.f16.f32 "
        "{%0,%1,%2,%3}, {%4,%5,%6,%7}, {%8,%9}, {%0,%1,%2,%3};"
        : "+f"(c[0]), "+f"(c[1]), "+f"(c[2]), "+f"(c[3])
        : "r"(a[0]), "r"(a[1]), "r"(a[2]), "r"(a[3]), "r"(b[0]), "r"(b[1]));
}
#define LDSM_X4(r0,r1,r2,r3,addr) \
    asm volatile("ldmatrix.sync.aligned.m8n8.x4.shared.b16 {%0,%1,%2,%3}, [%4];" \
        : "=r"(r0), "=r"(r1), "=r"(r2), "=r"(r3) : "r"(addr))
#define CP_ASYNC16(dst, src) \
    asm volatile("cp.async.cg.shared.global [%0], [%1], 16;" :: "r"(dst), "l"(src))
#define CP_COMMIT()  asm volatile("cp.async.commit_group;" ::: "memory")
#define CP_WAIT2()   asm volatile("cp.async.wait_group 2;" ::: "memory")
#define CP_WAIT1()   asm volatile("cp.async.wait_group 1;" ::: "memory")

// ===========================================================================
// Weight transpose + fp16 convert: out[n*K+k] = half(in[k*N+n])
// ===========================================================================
__global__ __launch_bounds__(256) void transpose_h_x4(
    const float* __restrict__ w0, const float* __restrict__ w1,
    const float* __restrict__ w2, const float* __restrict__ w3,
    __half* __restrict__ o0, __half* __restrict__ o1,
    __half* __restrict__ o2, __half* __restrict__ o3)
{
    const float* in  = (blockIdx.z == 0) ? w0 : (blockIdx.z == 1) ? w1 :
                       (blockIdx.z == 2) ? w2 : w3;
    __half*      out = (blockIdx.z == 0) ? o0 : (blockIdx.z == 1) ? o1 :
                       (blockIdx.z == 2) ? o2 : o3;
    __shared__ float t[32][33];
    int tx = threadIdx.x & 31;
    int ty = threadIdx.x >> 5;
    int x  = blockIdx.x*32 + tx;
    int y0 = blockIdx.y*32;
    #pragma unroll
    for (int j = ty; j < 32; j += 8) t[j][tx] = in[(size_t)(y0+j)*DM + x];
    __syncthreads();
    int xo  = y0 + tx;
    int yo0 = blockIdx.x*32;
    #pragma unroll
    for (int j = ty; j < 32; j += 8)
        out[(size_t)(yo0+j)*DM + xo] = __float2half_rn(t[tx][j]);
}

// ===========================================================================
// Elementwise fp32 -> fp16 preround for q,k,v inputs
// ===========================================================================
__global__ __launch_bounds__(256) void preround_h(
    const float* __restrict__ q, const float* __restrict__ k,
    const float* __restrict__ v,
    __half* __restrict__ oq, __half* __restrict__ ok, __half* __restrict__ ov)
{
    const float* in = (blockIdx.z == 0) ? q : (blockIdx.z == 1) ? k : v;
    __half*     out = (blockIdx.z == 0) ? oq : (blockIdx.z == 1) ? ok : ov;
    int idx = blockIdx.x*256 + threadIdx.x;
    float4 f = ((const float4*)in)[idx];
    uint2 u;
    u.x = pack_h2(f.x, f.y);
    u.y = pack_h2(f.z, f.w);
    ((uint2*)out)[idx] = u;
}

// ===========================================================================
// fp16 GEMM core: 128(M) x 128(N) CTA tile, 256 threads (8 warps, 4m x 2n),
// K-chunk 64 halves (128B rows), 3-stage cp.async, 2 CTAs/SM.
// Loop order: compute(c) -> barrier -> copy(c+3) into freed stage.
// mode 0: fp32 out; mode 1: half(x*scl); mode 2: transposed half out
// ===========================================================================
#define NCH      16
#define STG_B    32768                // A 16KB + B 16KB
#define GM_SMEM  (3*STG_B)            // 96 KB -> 2 CTAs/SM

__device__ __forceinline__ void gemm_core(
    const __half* __restrict__ A, const __half* __restrict__ WT,
    const float* __restrict__ bias, void* __restrict__ Cv,
    float scl, int mode, char* dsm)
{
    const uint32_t smb = smem_u32(dsm);

    const int tid  = threadIdx.x;
    const int wid  = tid >> 5;
    const int lane = tid & 31;
    const int wm   = wid >> 1;
    const int wn   = wid & 1;
    const int g    = lane >> 2;
    const int t    = lane & 3;
    const int rowBase = blockIdx.y * 128;
    const int colBase = blockIdx.x * 128;

    const int lr = lane & 7;
    const int lh = (lane >> 3) & 1;
    const int lg = lane >> 4;
    const int rowA0 = wm*32 + lr + 8*lh;
    const int rowB0 = wn*64 + lr + 8*lh;

    float acc[2][8][4];
    #pragma unroll
    for (int i = 0; i < 2; ++i)
        #pragma unroll
        for (int j = 0; j < 8; ++j)
            #pragma unroll
            for (int e = 0; e < 4; ++e) acc[i][j][e] = 0.f;

    auto copy_chunk = [&](int c, int stage) {
        const int k0 = c * 64;
        const uint32_t sb = smb + stage*STG_B;
        #pragma unroll
        for (int i = 0; i < 4; ++i) {
            int idx = tid + i*256;
            int row = idx >> 3;
            int gg  = idx & 7;
            uint32_t dst = sb + row*128 + 16*(gg ^ (row & 7));
            CP_ASYNC16(dst, A + (size_t)(rowBase+row)*DM + k0 + gg*8);
        }
        #pragma unroll
        for (int i = 0; i < 4; ++i) {
            int idx = tid + i*256;
            int row = idx >> 3;
            int gg  = idx & 7;
            uint32_t dst = sb + 16384 + row*128 + 16*(gg ^ (row & 7));
            CP_ASYNC16(dst, WT + (size_t)(colBase+row)*DM + k0 + gg*8);
        }
    };

    auto compute = [&](int stage) {
        const uint32_t sa  = smb + stage*STG_B;
        const uint32_t sbB = sa + 16384;
        #pragma unroll
        for (int ks = 0; ks < 4; ++ks) {
            const uint32_t swg = 16u * ((2*ks + lg) ^ lr);
            uint32_t a0[4], a1[4];
            LDSM_X4(a0[0],a0[1],a0[2],a0[3], sa + (rowA0     )*128 + swg);
            LDSM_X4(a1[0],a1[1],a1[2],a1[3], sa + (rowA0 + 16)*128 + swg);
            #pragma unroll
            for (int p = 0; p < 4; ++p) {
                uint32_t bq[4];
                LDSM_X4(bq[0],bq[1],bq[2],bq[3], sbB + (rowB0 + p*16)*128 + swg);
                uint32_t be[2] = {bq[0], bq[2]};
                uint32_t bo[2] = {bq[1], bq[3]};
                mma_f16(acc[0][2*p],   a0, be);
                mma_f16(acc[1][2*p],   a1, be);
                mma_f16(acc[0][2*p+1], a0, bo);
                mma_f16(acc[1][2*p+1], a1, bo);
            }
        }
    };

    copy_chunk(0, 0); CP_COMMIT();
    copy_chunk(1, 1); CP_COMMIT();
    copy_chunk(2, 2); CP_COMMIT();

    for (int c = 0; c < NCH; ++c) {
        CP_WAIT2();
        __syncthreads();                 // chunk c resident in stage c%3
        compute(c % 3);
        __syncthreads();                 // stage c%3 fully consumed
        if (c + 3 < NCH) copy_chunk(c + 3, c % 3);
        CP_COMMIT();
    }

    #pragma unroll
    for (int mt = 0; mt < 2; ++mt) {
        int r0 = rowBase + wm*32 + mt*16 + g;
        #pragma unroll
        for (int nt = 0; nt < 8; ++nt) {
            int col = colBase + wn*64 + nt*8 + 2*t;
            float b0 = bias[col], b1 = bias[col+1];
            float v00 = acc[mt][nt][0] + b0, v01 = acc[mt][nt][1] + b1;
            float v10 = acc[mt][nt][2] + b0, v11 = acc[mt][nt][3] + b1;
            if (mode == 0) {
                float* C = (float*)Cv;
                *(float2*)(C + (size_t)r0*DM + col)     = make_float2(v00, v01);
                *(float2*)(C + (size_t)(r0+8)*DM + col) = make_float2(v10, v11);
            } else if (mode == 1) {
                __half* C = (__half*)Cv;
                *(uint32_t*)(C + (size_t)r0*DM + col)     = pack_h2(v00*scl, v01*scl);
                *(uint32_t*)(C + (size_t)(r0+8)*DM + col) = pack_h2(v10*scl, v11*scl);
            } else {
                __half* C = (__half*)Cv;
                C[(size_t)col*MTOK + r0]         = __float2half_rn(v00);
                C[(size_t)(col+1)*MTOK + r0]     = __float2half_rn(v01);
                C[(size_t)col*MTOK + r0 + 8]     = __float2half_rn(v10);
                C[(size_t)(col+1)*MTOK + r0 + 8] = __float2half_rn(v11);
            }
        }
    }
}

__global__ __launch_bounds__(256, 2) void gemm_qkv(
    const __half* __restrict__ qi, const __half* __restrict__ ki, const __half* __restrict__ vi,
    const __half* __restrict__ wtq, const __half* __restrict__ wtk, const __half* __restrict__ wtv,
    const float* __restrict__ bq, const float* __restrict__ bk, const float* __restrict__ bv,
    __half* __restrict__ oq, __half* __restrict__ ok, __half* __restrict__ ovt)
{
    extern __shared__ char dsm[];
    const int z = blockIdx.z;
    const __half* A  = (z == 0) ? qi  : (z == 1) ? ki  : vi;
    const __half* WT = (z == 0) ? wtq : (z == 1) ? wtk : wtv;
    const float*  bb = (z == 0) ? bq  : (z == 1) ? bk  : bv;
    __half*       C  = (z == 0) ? oq  : (z == 1) ? ok  : ovt;
    float scl = (z == 0) ? 0.125f * LOG2E : 1.0f;
    int mode  = (z == 2) ? 2 : 1;
    gemm_core(A, WT, bb, C, scl, mode, dsm);
}

__global__ __launch_bounds__(256, 2) void gemm_out(
    const __half* __restrict__ A, const __half* __restrict__ WT,
    const float* __restrict__ bias, float* __restrict__ C)
{
    extern __shared__ char dsm[];
    gemm_core(A, WT, bias, C, 1.0f, 0, dsm);
}

// ===========================================================================
// fp16 tensor-core causal flash attention: 64 q-rows per CTA, 4 warps,
// 4 CTAs/SM. P in registers (FA2 fragment identity). Q re-LDSM'd per tile
// (no persistent Q regs -- RF is at the exact 128-reg ceiling).
// Rescale skipped when running max unchanged; l kept as per-thread partial,
// reduced once in epilogue.
// smem (40KB): [0,8K) Q; [8K + st*16K) st=0,1: K 8KB + VT 8KB
// ===========================================================================
#define AQ_ROWS 64
#define AKV     64
#define AOFF_KV 8192
#define ATTN_SMEM_TC (AOFF_KV + 2*16384)   // 40 KB

__global__ __launch_bounds__(128, 4) void attn_tc(
    const __half* __restrict__ Q, const __half* __restrict__ K,
    const __half* __restrict__ VT, __half* __restrict__ O)
{
    extern __shared__ char smraw[];
    const uint32_t smb = smem_u32(smraw);

    const int tid  = threadIdx.x;
    const int wid  = tid >> 5;            // 0..3
    const int lane = tid & 31;
    const int g    = lane >> 2;
    const int t4   = lane & 3;
    const int lr   = lane & 7;
    const int lh   = (lane >> 3) & 1;
    const int lg   = lane >> 4;
    const int h    = blockIdx.y;
    const int b    = blockIdx.z;
    const int q0   = (gridDim.x - 1 - blockIdx.x) * AQ_ROWS;  // longest first

    const int qi0 = q0 + wid*16 + g;
    const int qi1 = qi0 + 8;

    const __half* Qb  = Q + ((size_t)(b*TT))*DM + h*DKH;
    const __half* Kb  = K + ((size_t)(b*TT))*DM + h*DKH;
    const __half* VTb = VT + (size_t)(h*DKH)*MTOK + b*TT;

    const int ntiles = q0/AKV + 1;

    auto copy_kv = [&](int tile, int st) {
        const int k0 = tile * AKV;
        const uint32_t base = smb + AOFF_KV + st*16384;
        #pragma unroll
        for (int i = 0; i < 4; ++i) {           // K: 64 rows x 8 granules
            int idx = tid + i*128;
            int row = idx >> 3;
            int gg  = idx & 7;
            uint32_t dst = base + row*128 + 16*(gg ^ (row & 7));
            CP_ASYNC16(dst, Kb + (size_t)(k0+row)*DM + gg*8);
        }
        #pragma unroll
        for (int i = 0; i < 4; ++i) {           // VT: 64 d-rows x 8 granules
            int idx = tid + i*128;
            int row = idx >> 3;
            int gg  = idx & 7;
            uint32_t dst = base + 8192 + row*128 + 16*(gg ^ (row & 7));
            CP_ASYNC16(dst, VTb + (size_t)row*MTOK + k0 + gg*8);
        }
    };

    // ---- prologue: Q staging + first (up to) 2 KV tiles ----
    #pragma unroll
    for (int i = 0; i < 4; ++i) {               // Q: 64 rows x 8 granules
        int idx = tid + i*128;
        int row = idx >> 3;
        int gg  = idx & 7;
        uint32_t dst = smb + row*128 + 16*(gg ^ (row & 7));
        CP_ASYNC16(dst, Qb + (size_t)(q0+row)*DM + gg*8);
    }
    copy_kv(0, 0); CP_COMMIT();
    if (1 < ntiles) copy_kv(1, 1);
    CP_COMMIT();

    float oacc[8][4];
    #pragma unroll
    for (int nt = 0; nt < 8; ++nt)
        #pragma unroll
        for (int e = 0; e < 4; ++e) oacc[nt][e] = 0.f;
    float m0 = -1e30f, m1 = -1e30f, l0 = 0.f, l1 = 0.f;  // l: per-thread partials

    const int frow = lr + 8*lh;
    const int qrow = wid*16 + frow;

    for (int tk = 0; tk < ntiles; ++tk) {
        CP_WAIT1();
        __syncthreads();
        const uint32_t sK = smb + AOFF_KV + (tk & 1)*16384;
        const uint32_t sV = sK + 8192;

        // ---- S = Q @ K^T ----
        float sf[8][4];
        #pragma unroll
        for (int nt = 0; nt < 8; ++nt)
            #pragma unroll
            for (int e = 0; e < 4; ++e) sf[nt][e] = 0.f;
        #pragma unroll
        for (int ks = 0; ks < 4; ++ks) {
            const uint32_t swg = 16u * ((2*ks + lg) ^ lr);
            uint32_t qa[4];
            LDSM_X4(qa[0], qa[1], qa[2], qa[3], smb + qrow*128 + swg);
            #pragma unroll
            for (int p = 0; p < 4; ++p) {
                uint32_t bq[4];
                LDSM_X4(bq[0],bq[1],bq[2],bq[3], sK + (p*16 + frow)*128 + swg);
                uint32_t be[2] = {bq[0], bq[2]};
                uint32_t bo[2] = {bq[1], bq[3]};
                mma_f16(sf[2*p],   qa, be);
                mma_f16(sf[2*p+1], qa, bo);
            }
        }

        // ---- causal mask (last tile only) + row max ----
        float rmax0 = -1e30f, rmax1 = -1e30f;
        if (tk == ntiles - 1) {
            const int k0 = tk * AKV;
            #pragma unroll
            for (int nt = 0; nt < 8; ++nt) {
                int jb = k0 + nt*8 + 2*t4;
                #pragma unroll
                for (int e = 0; e < 4; ++e) {
                    int j = jb + (e & 1);
                    float v = sf[nt][e];
                    int qr = (e < 2) ? qi0 : qi1;
                    v = (j > qr) ? -1e30f : v;
                    sf[nt][e] = v;
                    if (e < 2) rmax0 = fmaxf(rmax0, v);
                    else       rmax1 = fmaxf(rmax1, v);
                }
            }
        } else {
            #pragma unroll
            for (int nt = 0; nt < 8; ++nt) {
                rmax0 = fmaxf(rmax0, fmaxf(sf[nt][0], sf[nt][1]));
                rmax1 = fmaxf(rmax1, fmaxf(sf[nt][2], sf[nt][3]));
            }
        }
        rmax0 = fmaxf(rmax0, __shfl_xor_sync(0xffffffff, rmax0, 1));
        rmax0 = fmaxf(rmax0, __shfl_xor_sync(0xffffffff, rmax0, 2));
        rmax1 = fmaxf(rmax1, __shfl_xor_sync(0xffffffff, rmax1, 1));
        rmax1 = fmaxf(rmax1, __shfl_xor_sync(0xffffffff, rmax1, 2));

        // ---- rescale only when the running max changes (c==1 skip exact) ----
        if (!__all_sync(0xffffffff, (rmax0 <= m0) & (rmax1 <= m1))) {
            float mn0 = fmaxf(m0, rmax0);
            float mn1 = fmaxf(m1, rmax1);
            float c0 = fexp2(m0 - mn0);
            float c1 = fexp2(m1 - mn1);
            m0 = mn0; m1 = mn1;
            l0 *= c0; l1 *= c1;
            #pragma unroll
            for (int nt = 0; nt < 8; ++nt) {
                oacc[nt][0] *= c0; oacc[nt][1] *= c0;
                oacc[nt][2] *= c1; oacc[nt][3] *= c1;
            }
        }

        // ---- exp -> P directly as PV A-fragments; l stays per-thread ----
        uint32_t pa[4][4];
        #pragma unroll
        for (int s = 0; s < 4; ++s) {
            float e00 = fexp2(sf[2*s  ][0] - m0), e01 = fexp2(sf[2*s  ][1] - m0);
            float e02 = fexp2(sf[2*s  ][2] - m1), e03 = fexp2(sf[2*s  ][3] - m1);
            float e10 = fexp2(sf[2*s+1][0] - m0), e11 = fexp2(sf[2*s+1][1] - m0);
            float e12 = fexp2(sf[2*s+1][2] - m1), e13 = fexp2(sf[2*s+1][3] - m1);
            l0 += (e00 + e01) + (e10 + e11);
            l1 += (e02 + e03) + (e12 + e13);
            pa[s][0] = pack_h2(e00, e01);
            pa[s][1] = pack_h2(e02, e03);
            pa[s][2] = pack_h2(e10, e11);
            pa[s][3] = pack_h2(e12, e13);
        }

        // ---- O += P @ V ----
        #pragma unroll
        for (int s = 0; s < 4; ++s) {
            const uint32_t swg = 16u * ((2*s + lg) ^ lr);
            #pragma unroll
            for (int p = 0; p < 4; ++p) {
                uint32_t bq[4];
                LDSM_X4(bq[0],bq[1],bq[2],bq[3], sV + (p*16 + frow)*128 + swg);
                uint32_t be[2] = {bq[0], bq[2]};
                uint32_t bo[2] = {bq[1], bq[3]};
                mma_f16(oacc[2*p],   pa[s], be);
                mma_f16(oacc[2*p+1], pa[s], bo);
            }
        }

        __syncthreads();
        if (tk + 2 < ntiles) copy_kv(tk + 2, tk & 1);
        CP_COMMIT();
    }

    // ---- epilogue: single l reduction, normalize, store ----
    l0 += __shfl_xor_sync(0xffffffff, l0, 1);
    l0 += __shfl_xor_sync(0xffffffff, l0, 2);
    l1 += __shfl_xor_sync(0xffffffff, l1, 1);
    l1 += __shfl_xor_sync(0xffffffff, l1, 2);
    const float i0 = 1.f / l0;
    const float i1 = 1.f / l1;
    __half* Ob = O + ((size_t)(b*TT))*DM + h*DKH;
    #pragma unroll
    for (int nt = 0; nt < 8; ++nt) {
        int d = nt*8 + 2*t4;
        *(uint32_t*)(Ob + (size_t)qi0*DM + d) = pack_h2(oacc[nt][0]*i0, oacc[nt][1]*i0);
        *(uint32_t*)(Ob + (size_t)qi1*DM + d) = pack_h2(oacc[nt][2]*i1, oacc[nt][3]*i1);
    }
}

// ===========================================================================
extern "C" void kernel_launch(void* const* d_in, const int* in_sizes, int n_in,
                              void* d_out, int out_size)
{
    const float* q  = (const float*)d_in[0];
    const float* k  = (const float*)d_in[1];
    const float* v  = (const float*)d_in[2];
    const float* wq = (const float*)d_in[4];
    const float* bq = (const float*)d_in[5];
    const float* wk = (const float*)d_in[6];
    const float* bk = (const float*)d_in[7];
    const float* wv = (const float*)d_in[8];
    const float* bv = (const float*)d_in[9];
    const float* wo = (const float*)d_in[10];
    const float* bo = (const float*)d_in[11];
    float* out = (float*)d_out;

    __half *gqi, *gki, *gvi, *gq, *gk, *gvt, *gc, *gwt;
    cudaGetSymbolAddress((void**)&gqi, g_QI);
    cudaGetSymbolAddress((void**)&gki, g_KI);
    cudaGetSymbolAddress((void**)&gvi, g_VI);
    cudaGetSymbolAddress((void**)&gq,  g_Q);
    cudaGetSymbolAddress((void**)&gk,  g_K);
    cudaGetSymbolAddress((void**)&gvt, g_VT);
    cudaGetSymbolAddress((void**)&gc,  g_C);
    cudaGetSymbolAddress((void**)&gwt, g_WT);
    __half* wtq = gwt;
    __half* wtk = gwt + (size_t)DM*DM;
    __half* wtv = gwt + (size_t)2*DM*DM;
    __half* wto = gwt + (size_t)3*DM*DM;

    cudaFuncSetAttribute(attn_tc, cudaFuncAttributeMaxDynamicSharedMemorySize, ATTN_SMEM_TC);
    cudaFuncSetAttribute(gemm_qkv, cudaFuncAttributeMaxDynamicSharedMemorySize, GM_SMEM);
    cudaFuncSetAttribute(gemm_out, cudaFuncAttributeMaxDynamicSharedMemorySize, GM_SMEM);

    dim3 tgrid(DM/32, DM/32, 4);
    transpose_h_x4<<<tgrid, 256>>>(wq, wk, wv, wo, wtq, wtk, wtv, wto);

    dim3 pgrid(MTOK*DM/4/256, 1, 3);
    preround_h<<<pgrid, 256>>>(q, k, v, gqi, gki, gvi);

    dim3 qkvgrid(DM/128, MTOK/128, 3);   // (8, 32, 3) = 768 CTAs, 2/SM
    gemm_qkv<<<qkvgrid, 256, GM_SMEM>>>(gqi, gki, gvi, wtq, wtk, wtv,
                                        bq, bk, bv, gq, gk, gvt);

    dim3 agrid(TT/AQ_ROWS, NH, BB);      // (32, 16, 2) = 1024 CTAs, 4/SM
    attn_tc<<<agrid, 128, ATTN_SMEM_TC>>>(gq, gk, gvt, gc);

    dim3 ogrid(DM/128, MTOK/128);        // (8, 32) = 256 CTAs = 1 full wave
    gemm_out<<<ogrid, 256, GM_SMEM>>>(gc, wto, bo, out);
}